// round 3
// baseline (speedup 1.0000x reference)
#include <cuda_runtime.h>
#include <cuda_bf16.h>
#include <stdint.h>

#define N_NODES 50000
#define N_EDGES 400000
#define F_IN    128
#define F_HID   512
#define F_OUT   250

// ---------------- scratch (static __device__ — no allocation) ----------------
__device__ int   g_is32;
__device__ int   g_src[N_EDGES];
__device__ int   g_dst[N_EDGES];
__device__ int   g_deg[N_NODES];
__device__ float g_dinv[N_NODES];
__device__ float g_aggx[(size_t)N_NODES * F_IN];   // A·x        25.6 MB
__device__ float g_h1  [(size_t)N_NODES * F_HID];  // relu(...)  102.4 MB
__device__ float g_t2  [(size_t)N_NODES * F_OUT];  // h1·W2      50 MB

// ---------------- edge_index dtype sniff + normalize to int32 ----------------
// JAX default config disables x64: jnp.int64 silently becomes int32. Detect at
// runtime: read first 4096 words as int64; any value outside [0, N_NODES)
// means the buffer is actually int32 (two packed indices per word).
__global__ void detect_kernel(const void* __restrict__ ei_raw) {
    const long long* p = (const long long*)ei_raw;
    int bad = 0;
    for (int i = threadIdx.x; i < 4096; i += blockDim.x) {
        long long v = p[i];
        if (v < 0 || v >= N_NODES) bad = 1;
    }
    int any = __syncthreads_or(bad);
    if (threadIdx.x == 0) g_is32 = any;   // 1 => int32 layout, 0 => int64
}

__global__ void convert_kernel(const void* __restrict__ ei_raw) {
    int e = blockIdx.x * blockDim.x + threadIdx.x;
    if (e >= N_EDGES) return;
    if (g_is32) {
        const int* p = (const int*)ei_raw;
        g_src[e] = p[e];
        g_dst[e] = p[N_EDGES + e];
    } else {
        const long long* p = (const long long*)ei_raw;
        g_src[e] = (int)p[e];
        g_dst[e] = (int)p[N_EDGES + e];
    }
}

// ---------------- degree / norm ----------------
__global__ void deg_init_kernel() {
    int i = blockIdx.x * blockDim.x + threadIdx.x;
    if (i < N_NODES) g_deg[i] = 1;   // self-loop
}

__global__ void deg_count_kernel() {
    int e = blockIdx.x * blockDim.x + threadIdx.x;
    if (e < N_EDGES) atomicAdd(&g_deg[g_dst[e]], 1);
}

__global__ void dinv_kernel() {
    int i = blockIdx.x * blockDim.x + threadIdx.x;
    if (i < N_NODES) g_dinv[i] = rsqrtf((float)g_deg[i]);
}

// ---------------- layer-1 aggregation: aggx = A_hat * x (128-wide) ----------------
__global__ void aggx_init_kernel(const float* __restrict__ x) {
    int idx = blockIdx.x * blockDim.x + threadIdx.x;       // over N*32 float4 chunks
    if (idx >= N_NODES * (F_IN / 4)) return;
    int node = idx >> 5;                                    // /32
    float w = g_dinv[node]; w *= w;
    float4 v = reinterpret_cast<const float4*>(x)[idx];
    float4* o = reinterpret_cast<float4*>(g_aggx);
    o[idx] = make_float4(w * v.x, w * v.y, w * v.z, w * v.w);
}

// warp-per-edge, float4 lanes: aggx[dst] += dinv[src]*dinv[dst] * x[src]
__global__ void scatter1_kernel(const float* __restrict__ x) {
    int tid = blockIdx.x * blockDim.x + threadIdx.x;
    int e    = tid >> 5;          // 32 float4 chunks per edge
    int lane = tid & 31;
    if (e >= N_EDGES) return;
    int s = g_src[e], d = g_dst[e];
    float w = g_dinv[s] * g_dinv[d];
    float4 v = reinterpret_cast<const float4*>(x)[(size_t)s * 32 + lane];
    float* o = g_aggx + (size_t)d * F_IN + lane * 4;
    atomicAdd(o + 0, w * v.x);
    atomicAdd(o + 1, w * v.y);
    atomicAdd(o + 2, w * v.z);
    atomicAdd(o + 3, w * v.w);
}

// ---------------- tiled fp32 GEMM: C = A[MxK] * B[KxN] (+bias, relu) ----------------
// SEL resolves A/C device-global buffers in DEVICE code.
//   SEL=0: A=g_aggx, C=g_h1   (layer 1)
//   SEL=1: A=g_h1,   C=g_t2   (layer 2)
template<bool RELU, bool BIAS, int SEL>
__global__ __launch_bounds__(256)
void sgemm_kernel(int M, int N, int K,
                  const float* __restrict__ B,
                  const float* __restrict__ bias) {
    const float* A = (SEL == 0) ? g_aggx : g_h1;
    float*       C = (SEL == 0) ? g_h1   : g_t2;

    constexpr int BM = 128, BN = 64, BK = 16, TM = 8, TN = 4;
    __shared__ float As[BK][BM + 4];
    __shared__ float Bs[BK][BN + 4];
    const int tid = threadIdx.x;            // 256 threads
    const int tx = tid & 15, ty = tid >> 4; // 16 x 16
    const int row0 = blockIdx.y * BM;
    const int col0 = blockIdx.x * BN;

    float acc[TM][TN] = {};

    for (int kk = 0; kk < K; kk += BK) {
        // A tile: BM x BK (K multiple of BK; row guard only)
        #pragma unroll
        for (int i = tid; i < BM * BK; i += 256) {
            int r = i >> 4, c = i & 15;      // BK = 16
            int gr = row0 + r;
            As[c][r] = (gr < M) ? A[(size_t)gr * K + kk + c] : 0.f;
        }
        // B tile: BK x BN
        #pragma unroll
        for (int i = tid; i < BK * BN; i += 256) {
            int r = i >> 6, c = i & 63;      // BN = 64
            int gc = col0 + c;
            Bs[r][c] = (gc < N) ? B[(size_t)(kk + r) * N + gc] : 0.f;
        }
        __syncthreads();

        #pragma unroll
        for (int k = 0; k < BK; k++) {
            float a[TM], b[TN];
            #pragma unroll
            for (int i = 0; i < TM; i++) a[i] = As[k][ty * TM + i];
            #pragma unroll
            for (int j = 0; j < TN; j++) b[j] = Bs[k][tx * TN + j];
            #pragma unroll
            for (int i = 0; i < TM; i++)
                #pragma unroll
                for (int j = 0; j < TN; j++)
                    acc[i][j] = fmaf(a[i], b[j], acc[i][j]);
        }
        __syncthreads();
    }

    #pragma unroll
    for (int i = 0; i < TM; i++) {
        int gr = row0 + ty * TM + i;
        if (gr >= M) continue;
        #pragma unroll
        for (int j = 0; j < TN; j++) {
            int gc = col0 + tx * TN + j;
            if (gc >= N) continue;
            float v = acc[i][j];
            if (BIAS) v += bias[gc];
            if (RELU) v = fmaxf(v, 0.f);
            C[(size_t)gr * N + gc] = v;
        }
    }
}

// ---------------- layer-2 aggregation (250-wide, on GEMM output t2) ----------------
__global__ void out_init_kernel(float* __restrict__ out) {
    int idx = blockIdx.x * blockDim.x + threadIdx.x;        // over N*125 float2
    if (idx >= N_NODES * (F_OUT / 2)) return;
    int node = idx / 125;
    float w = g_dinv[node]; w *= w;
    float2 v = reinterpret_cast<const float2*>(g_t2)[idx];
    reinterpret_cast<float2*>(out)[idx] = make_float2(w * v.x, w * v.y);
}

// one block (128 thr) per edge; threads 0..124 handle float2 chunks
__global__ void scatter2_kernel(float* __restrict__ out) {
    int e = blockIdx.x;
    int c = threadIdx.x;
    if (c >= 125) return;
    int s = g_src[e], d = g_dst[e];
    float w = g_dinv[s] * g_dinv[d];
    float2 v = reinterpret_cast<const float2*>(g_t2)[(size_t)s * 125 + c];
    float* o = out + (size_t)d * F_OUT + c * 2;
    atomicAdd(o + 0, w * v.x);
    atomicAdd(o + 1, w * v.y);
}

__global__ void bias_relu_kernel(const float* __restrict__ b2, float* __restrict__ out) {
    int idx = blockIdx.x * blockDim.x + threadIdx.x;
    if (idx >= N_NODES * F_OUT) return;
    int col = idx % F_OUT;
    out[idx] = fmaxf(out[idx] + b2[col], 0.f);
}

// ---------------- launch ----------------
extern "C" void kernel_launch(void* const* d_in, const int* in_sizes, int n_in,
                              void* d_out, int out_size) {
    const float* x  = (const float*)d_in[0];
    const void*  ei = d_in[1];                 // edge_index: int32 OR int64, sniffed on device
    const float* W1 = (const float*)d_in[2];
    const float* b1 = (const float*)d_in[3];
    const float* W2 = (const float*)d_in[4];
    const float* b2 = (const float*)d_in[5];
    float* out = (float*)d_out;

    // normalize edge_index -> int32 g_src/g_dst
    detect_kernel<<<1, 256>>>(ei);
    convert_kernel<<<(N_EDGES + 255) / 256, 256>>>(ei);

    // degrees + norm
    deg_init_kernel<<<(N_NODES + 255) / 256, 256>>>();
    deg_count_kernel<<<(N_EDGES + 255) / 256, 256>>>();
    dinv_kernel<<<(N_NODES + 255) / 256, 256>>>();

    // layer 1: aggregate x first (A·x, 128-wide), then GEMM+bias+relu
    {
        int n4 = N_NODES * (F_IN / 4);
        aggx_init_kernel<<<(n4 + 255) / 256, 256>>>(x);
        int tot = N_EDGES * 32;
        scatter1_kernel<<<(tot + 255) / 256, 256>>>(x);
        dim3 grid((F_HID + 63) / 64, (N_NODES + 127) / 128);
        sgemm_kernel<true, true, 0><<<grid, 256>>>(N_NODES, F_HID, F_IN, W1, b1);
    }

    // layer 2: GEMM first (512->250), then aggregate, then bias+relu
    {
        dim3 grid((F_OUT + 63) / 64, (N_NODES + 127) / 128);
        sgemm_kernel<false, false, 1><<<grid, 256>>>(N_NODES, F_OUT, F_HID, W2, nullptr);
        int n2 = N_NODES * (F_OUT / 2);
        out_init_kernel<<<(n2 + 255) / 256, 256>>>(out);
        scatter2_kernel<<<N_EDGES, 128>>>(out);
        int tot = N_NODES * F_OUT;
        bias_relu_kernel<<<(tot + 255) / 256, 256>>>(b2, out);
    }
}